// round 2
// baseline (speedup 1.0000x reference)
#include <cuda_runtime.h>
#include <cuda_bf16.h>

// out[(half*128 + 2f), i]   = sin(coord[half][i] * inv_freq[f])
// out[(half*128 + 2f+1), i] = cos(coord[half][i] * inv_freq[f])
// half = 0 -> Y row, half = 1 -> X row. num = 262144, 64 freqs, out (256, num).
//
// R2: __sincosf hardware fast path (RRO+MUFU) instead of software sincosf;
//     8 elements per thread (2x float4 load, 4x float4 store).

__global__ __launch_bounds__(128)
void pe_offgrid_kernel(const float* __restrict__ YX,
                       const float* __restrict__ inv_freq,
                       float* __restrict__ out,
                       int num) {
    int r = blockIdx.y;            // 0..127 : (half, freq)
    int half = r >> 6;             // 0 or 1
    int f = r & 63;                // 0..63
    float freq = __ldg(inv_freq + f);

    int i0 = (blockIdx.x * blockDim.x + threadIdx.x) << 3;  // 8 elems per thread

    const float4* src = reinterpret_cast<const float4*>(YX + (size_t)half * num + i0);
    const float4 c4a = src[0];
    const float4 c4b = src[1];

    float4 sa, ca, sb, cb;
    __sincosf(c4a.x * freq, &sa.x, &ca.x);
    __sincosf(c4a.y * freq, &sa.y, &ca.y);
    __sincosf(c4a.z * freq, &sa.z, &ca.z);
    __sincosf(c4a.w * freq, &sa.w, &ca.w);
    __sincosf(c4b.x * freq, &sb.x, &cb.x);
    __sincosf(c4b.y * freq, &sb.y, &cb.y);
    __sincosf(c4b.z * freq, &sb.z, &cb.z);
    __sincosf(c4b.w * freq, &sb.w, &cb.w);

    float* base = out + ((size_t)(half * 128 + 2 * f)) * (size_t)num + i0;
    float4* sin_row = reinterpret_cast<float4*>(base);
    float4* cos_row = reinterpret_cast<float4*>(base + num);
    sin_row[0] = sa;
    sin_row[1] = sb;
    cos_row[0] = ca;
    cos_row[1] = cb;
}

extern "C" void kernel_launch(void* const* d_in, const int* in_sizes, int n_in,
                              void* d_out, int out_size) {
    const float* YX       = (const float*)d_in[0];   // (2, num) fp32
    const float* inv_freq = (const float*)d_in[1];   // (64,)   fp32
    float* out            = (float*)d_out;           // (256, num) fp32

    int num = in_sizes[0] / 2;                       // 262144

    const int TPB = 128;
    int i_blocks = num / (TPB * 8);                  // 256 (num divisible)
    dim3 grid(i_blocks, 128);                        // 128 = 2 halves * 64 freqs
    pe_offgrid_kernel<<<grid, TPB>>>(YX, inv_freq, out, num);
}

// round 3
// speedup vs baseline: 1.6172x; 1.6172x over previous
#include <cuda_runtime.h>
#include <cuda_bf16.h>

// out[(half*128 + 2f), i]   = sin(coord[half][i] * inv_freq[f])
// out[(half*128 + 2f+1), i] = cos(coord[half][i] * inv_freq[f])
// half = 0 -> Y rows (0..127), half = 1 -> X rows (128..255).
//
// R3: load 4 coords once per thread, loop over FPG=8 frequencies reusing them
//     (cuts redundant input reads 8x, gives ILP to hide MUFU/store latency),
//     fast __sincosf path, float4 stores.

#define FPG 8   // freqs per CTA group

__global__ __launch_bounds__(128)
void pe_offgrid_kernel(const float* __restrict__ YX,
                       const float* __restrict__ inv_freq,
                       float* __restrict__ out,
                       int num) {
    int g = blockIdx.y;                 // 0..(2*64/FPG - 1)
    int half = g >= (64 / FPG);         // 0 or 1
    int fbase = (g - half * (64 / FPG)) * FPG;

    int i0 = (blockIdx.x * blockDim.x + threadIdx.x) << 2;  // 4 elems/thread

    const float4 c4 = *reinterpret_cast<const float4*>(YX + (size_t)half * num + i0);

    float* hbase = out + (size_t)(half * 128 + 2 * fbase) * (size_t)num + i0;

    #pragma unroll
    for (int k = 0; k < FPG; k++) {
        float freq = __ldg(inv_freq + fbase + k);
        float4 s, c;
        __sincosf(c4.x * freq, &s.x, &c.x);
        __sincosf(c4.y * freq, &s.y, &c.y);
        __sincosf(c4.z * freq, &s.z, &c.z);
        __sincosf(c4.w * freq, &s.w, &c.w);
        float* row = hbase + (size_t)(2 * k) * (size_t)num;
        *reinterpret_cast<float4*>(row)       = s;   // sin row
        *reinterpret_cast<float4*>(row + num) = c;   // cos row
    }
}

extern "C" void kernel_launch(void* const* d_in, const int* in_sizes, int n_in,
                              void* d_out, int out_size) {
    const float* YX       = (const float*)d_in[0];   // (2, num) fp32
    const float* inv_freq = (const float*)d_in[1];   // (64,)   fp32
    float* out            = (float*)d_out;           // (256, num) fp32

    int num = in_sizes[0] / 2;                       // 262144

    const int TPB = 128;
    int i_blocks = num / (TPB * 4);                  // 512
    dim3 grid(i_blocks, 2 * 64 / FPG);               // 512 x 16 = 8192 CTAs
    pe_offgrid_kernel<<<grid, TPB>>>(YX, inv_freq, out, num);
}

// round 4
// speedup vs baseline: 1.6718x; 1.0337x over previous
#include <cuda_runtime.h>
#include <cuda_bf16.h>

// out[(half*128 + 2f), i]   = sin(coord[half][i] * inv_freq[f])
// out[(half*128 + 2f+1), i] = cos(coord[half][i] * inv_freq[f])
// half = 0 -> Y rows (0..127), half = 1 -> X rows (128..255).
//
// R4: R3 + 256-thread CTAs (more store MLP in flight) + __stcs streaming
//     stores (evict-first: output is write-once, keep it from churning L2).

#define FPG 8   // freqs per CTA group

__global__ __launch_bounds__(256)
void pe_offgrid_kernel(const float* __restrict__ YX,
                       const float* __restrict__ inv_freq,
                       float* __restrict__ out,
                       int num) {
    int g = blockIdx.y;                 // 0..(2*64/FPG - 1)
    int half = g >= (64 / FPG);         // 0 or 1
    int fbase = (g - half * (64 / FPG)) * FPG;

    int i0 = (blockIdx.x * blockDim.x + threadIdx.x) << 2;  // 4 elems/thread

    const float4 c4 = *reinterpret_cast<const float4*>(YX + (size_t)half * num + i0);

    float* hbase = out + (size_t)(half * 128 + 2 * fbase) * (size_t)num + i0;

    #pragma unroll
    for (int k = 0; k < FPG; k++) {
        float freq = __ldg(inv_freq + fbase + k);
        float4 s, c;
        __sincosf(c4.x * freq, &s.x, &c.x);
        __sincosf(c4.y * freq, &s.y, &c.y);
        __sincosf(c4.z * freq, &s.z, &c.z);
        __sincosf(c4.w * freq, &s.w, &c.w);
        float* row = hbase + (size_t)(2 * k) * (size_t)num;
        __stcs(reinterpret_cast<float4*>(row), s);        // sin row (streaming)
        __stcs(reinterpret_cast<float4*>(row + num), c);  // cos row (streaming)
    }
}

extern "C" void kernel_launch(void* const* d_in, const int* in_sizes, int n_in,
                              void* d_out, int out_size) {
    const float* YX       = (const float*)d_in[0];   // (2, num) fp32
    const float* inv_freq = (const float*)d_in[1];   // (64,)   fp32
    float* out            = (float*)d_out;           // (256, num) fp32

    int num = in_sizes[0] / 2;                       // 262144

    const int TPB = 256;
    int i_blocks = num / (TPB * 4);                  // 256
    dim3 grid(i_blocks, 2 * 64 / FPG);               // 256 x 16 = 4096 CTAs
    pe_offgrid_kernel<<<grid, TPB>>>(YX, inv_freq, out, num);
}